// round 7
// baseline (speedup 1.0000x reference)
#include <cuda_runtime.h>
#include <cuda_fp16.h>

#define N_NODES 50000
#define N_EDGES 625000
#define D_FEAT  128
#define K_HOPS  10
#define SZ      (N_NODES * D_FEAT)

#define SCAN_TILE 512
#define N_TILES   ((N_NODES + SCAN_TILE - 1) / SCAN_TILE)   // 98

// ---------------------------------------------------------------------------
// Scratch (device globals — no allocation allowed anywhere)
// ---------------------------------------------------------------------------
__device__ __half g_hh[(size_t)K_HOPS * SZ];  // h_k (scaled) at slot k-1, 128 MB
__device__ __half g_xh[SZ];                   // fp16(x), 12.8 MB
__device__ int    g_deg[N_NODES];
__device__ int    g_rowptr[N_NODES + 1];
__device__ int    g_cursor[N_NODES];
__device__ int    g_col[N_EDGES];
__device__ float  g_w[K_HOPS + 1];
__device__ int    g_is64;
__device__ int    g_tilesum[N_TILES];
__device__ int    g_tileoff[N_TILES];
__device__ float  g_S[K_HOPS + 1];   // S[k] = max |stored h_k| (S[0] = max|x|)
__device__ int    g_d[K_HOPS + 1];   // per-hop scale exponent d_k
__device__ int    g_maxdeg;

__device__ __forceinline__ void atomicMaxF(float* addr, float v) {
    atomicMax((int*)addr, __float_as_int(v));   // valid: non-negative floats
}

// ---------------------------------------------------------------------------
// 0) dtype detect + softmax(att) + zero per-launch scalars
// ---------------------------------------------------------------------------
__global__ void prep_kernel(const void* ei, const float* __restrict__ att) {
    if (threadIdx.x == 0 && blockIdx.x == 0) {
        const long long* p = (const long long*)ei;
        int is64 = 1;
        for (int i = 0; i < 64; i++) {
            long long v = p[i];
            if (v < 0 || v >= (long long)N_NODES) { is64 = 0; break; }
        }
        g_is64 = is64;

        float m = -1e30f;
        for (int i = 0; i <= K_HOPS; i++) m = fmaxf(m, att[i]);
        float e[K_HOPS + 1];
        float s = 0.f;
        for (int i = 0; i <= K_HOPS; i++) { e[i] = __expf(att[i] - m); s += e[i]; }
        float inv = 1.f / s;
        for (int i = 0; i <= K_HOPS; i++) g_w[i] = e[i] * inv;

        for (int i = 0; i <= K_HOPS; i++) { g_S[i] = 0.f; g_d[i] = 0; }
        g_maxdeg = 0;
    }
}

// fused: x -> fp16 g_xh, and max|x| -> g_S[0]
__global__ void __launch_bounds__(256)
quantize_x_kernel(const float* __restrict__ x) {
    float m = 0.f;
    for (int i = blockIdx.x * blockDim.x + threadIdx.x; i < SZ / 4;
         i += gridDim.x * blockDim.x) {
        float4 v = __ldg(&((const float4*)x)[i]);
        m = fmaxf(m, fmaxf(fmaxf(fabsf(v.x), fabsf(v.y)),
                           fmaxf(fabsf(v.z), fabsf(v.w))));
        __half2 h01 = __floats2half2_rn(v.x, v.y);
        __half2 h23 = __floats2half2_rn(v.z, v.w);
        uint2 st;
        st.x = *(unsigned*)&h01;
        st.y = *(unsigned*)&h23;
        ((uint2*)g_xh)[i] = st;
    }
    for (int off = 16; off > 0; off >>= 1)
        m = fmaxf(m, __shfl_down_sync(0xFFFFFFFFu, m, off));
    if ((threadIdx.x & 31) == 0) atomicMaxF(&g_S[0], m);
}

// ---------------------------------------------------------------------------
// CSR build
// ---------------------------------------------------------------------------
__global__ void zero_deg_kernel() {
    int i = blockIdx.x * blockDim.x + threadIdx.x;
    if (i < N_NODES) g_deg[i] = 0;
}

__global__ void hist_kernel(const void* __restrict__ ei) {
    int t = blockIdx.x * blockDim.x + threadIdx.x;
    int e = t * 2;
    if (e >= N_EDGES) return;
    if (g_is64) {
        const longlong2* p = (const longlong2*)((const long long*)ei + N_EDGES);
        longlong2 d = p[t];
        atomicAdd(&g_deg[(int)d.x], 1);
        if (e + 1 < N_EDGES) atomicAdd(&g_deg[(int)d.y], 1);
    } else {
        const int2* p = (const int2*)((const int*)ei + N_EDGES);
        int2 d = p[t];
        atomicAdd(&g_deg[d.x], 1);
        if (e + 1 < N_EDGES) atomicAdd(&g_deg[d.y], 1);
    }
}

__global__ void __launch_bounds__(SCAN_TILE)
scan_reduce_kernel() {
    __shared__ int wsum[SCAN_TILE / 32];
    int i = blockIdx.x * SCAN_TILE + threadIdx.x;
    int v = (i < N_NODES) ? g_deg[i] : 0;
    int mx = v;
    for (int off = 16; off > 0; off >>= 1) {
        v  += __shfl_down_sync(0xFFFFFFFFu, v,  off);
        mx  = max(mx, __shfl_down_sync(0xFFFFFFFFu, mx, off));
    }
    int wid = threadIdx.x >> 5;
    if ((threadIdx.x & 31) == 0) { wsum[wid] = v; atomicMax(&g_maxdeg, mx); }
    __syncthreads();
    if (wid == 0) {
        int lane = threadIdx.x & 31;
        int s = (lane < SCAN_TILE / 32) ? wsum[lane] : 0;
        for (int off = 16; off > 0; off >>= 1)
            s += __shfl_down_sync(0xFFFFFFFFu, s, off);
        if (lane == 0) g_tilesum[blockIdx.x] = s;
    }
}

__global__ void scan_tiles_kernel() {
    __shared__ int wtot[4];
    int tid  = threadIdx.x;
    int lane = tid & 31;
    int wid  = tid >> 5;
    int v = (tid < N_TILES) ? g_tilesum[tid] : 0;
    int incl = v;
    for (int off = 1; off < 32; off <<= 1) {
        int u = __shfl_up_sync(0xFFFFFFFFu, incl, off);
        if (lane >= off) incl += u;
    }
    if (lane == 31) wtot[wid] = incl;
    __syncthreads();
    int base = 0;
    for (int w = 0; w < wid; w++) base += wtot[w];
    int excl = base + incl - v;
    if (tid < N_TILES) g_tileoff[tid] = excl;
    if (tid == N_TILES - 1) g_rowptr[N_NODES] = excl + v;
}

__global__ void __launch_bounds__(SCAN_TILE)
scan_final_kernel() {
    __shared__ int wtot[SCAN_TILE / 32];
    int i    = blockIdx.x * SCAN_TILE + threadIdx.x;
    int lane = threadIdx.x & 31;
    int wid  = threadIdx.x >> 5;

    int v = (i < N_NODES) ? g_deg[i] : 0;
    int incl = v;
    for (int off = 1; off < 32; off <<= 1) {
        int u = __shfl_up_sync(0xFFFFFFFFu, incl, off);
        if (lane >= off) incl += u;
    }
    if (lane == 31) wtot[wid] = incl;
    __syncthreads();
    if (wid == 0) {
        int s = (lane < SCAN_TILE / 32) ? wtot[lane] : 0;
        int si = s;
        for (int off = 1; off < 32; off <<= 1) {
            int u = __shfl_up_sync(0xFFFFFFFFu, si, off);
            if (lane >= off) si += u;
        }
        if (lane < SCAN_TILE / 32) wtot[lane] = si - s;
    }
    __syncthreads();

    if (i < N_NODES) {
        int excl = g_tileoff[blockIdx.x] + wtot[wid] + incl - v;
        g_rowptr[i] = excl;
        g_cursor[i] = excl;
    }
}

__global__ void scatter_kernel(const void* __restrict__ ei) {
    int t = blockIdx.x * blockDim.x + threadIdx.x;
    int e = t * 2;
    if (e >= N_EDGES) return;
    if (g_is64) {
        const long long* p = (const long long*)ei;
        longlong2 sp = ((const longlong2*)p)[t];
        longlong2 dp = ((const longlong2*)(p + N_EDGES))[t];
        int q0 = atomicAdd(&g_cursor[(int)dp.x], 1);
        g_col[q0] = (int)sp.x;
        if (e + 1 < N_EDGES) {
            int q1 = atomicAdd(&g_cursor[(int)dp.y], 1);
            g_col[q1] = (int)sp.y;
        }
    } else {
        const int* p = (const int*)ei;
        int2 sp = ((const int2*)p)[t];
        int2 dp = ((const int2*)(p + N_EDGES))[t];
        int q0 = atomicAdd(&g_cursor[dp.x], 1);
        g_col[q0] = sp.x;
        if (e + 1 < N_EDGES) {
            int q1 = atomicAdd(&g_cursor[dp.y], 1);
            g_col[q1] = sp.y;
        }
    }
}

// ---------------------------------------------------------------------------
// propagation hop k (warp-per-node), fp16 storage, masked unroll-8 gather:
//   stored_k = (A * stored_{k-1}) * 2^{-d_k}
// All hops read fp16 (hop 1 reads g_xh). Lane L owns features [4L, 4L+4):
// one uint2 (8B) load per edge row per lane -> 256B coalesced per edge.
// Chunks of 8 predicated loads keep MLP=8 even in the tail.
// ---------------------------------------------------------------------------
__global__ void __launch_bounds__(512)
prop_kernel(int k) {
    const int gwarp = (blockIdx.x * blockDim.x + threadIdx.x) >> 5;
    const int lane  = threadIdx.x & 31;
    const int wid   = threadIdx.x >> 5;
    __shared__ float smax[16];

    float4 a0 = make_float4(0.f, 0.f, 0.f, 0.f);
    float4 a1 = make_float4(0.f, 0.f, 0.f, 0.f);

    if (gwarp < N_NODES) {
        const __half* hin = (k == 1) ? g_xh : (g_hh + (size_t)(k - 2) * SZ);
        const uint2* __restrict__ hv = (const uint2*)hin;
        const int beg = g_rowptr[gwarp];
        const int end = g_rowptr[gwarp + 1];

        for (int e0 = beg; e0 < end; e0 += 8) {
            const int rem = end - e0;
            int  s[8];
            uint2 u[8];
#pragma unroll
            for (int j = 0; j < 8; j++)
                s[j] = (j < rem) ? __ldg(&g_col[e0 + j]) : 0;
#pragma unroll
            for (int j = 0; j < 8; j++)
                u[j] = (j < rem) ? __ldg(&hv[s[j] * 32 + lane])
                                 : make_uint2(0u, 0u);
#pragma unroll
            for (int j = 0; j < 8; j++) {
                float2 p0 = __half22float2(*(__half2*)&u[j].x);
                float2 p1 = __half22float2(*(__half2*)&u[j].y);
                if (j & 1) {
                    a1.x += p0.x; a1.y += p0.y; a1.z += p1.x; a1.w += p1.y;
                } else {
                    a0.x += p0.x; a0.y += p0.y; a0.z += p1.x; a0.w += p1.y;
                }
            }
        }
    }
    float4 acc = make_float4(a0.x + a1.x, a0.y + a1.y, a0.z + a1.z, a0.w + a1.w);

    // deterministic per-hop scale from previous hop's measured max
    float bound = g_S[k - 1] * (float)g_maxdeg;
    int d = 0;
    if (bound > 32768.f) d = (int)ceilf(log2f(bound * (1.f / 32768.f)));
    float sc = exp2f(-(float)d);          // exact power of 2
    acc.x *= sc; acc.y *= sc; acc.z *= sc; acc.w *= sc;

    // track max |stored_k|
    float m = fmaxf(fmaxf(fabsf(acc.x), fabsf(acc.y)),
                    fmaxf(fabsf(acc.z), fabsf(acc.w)));
    for (int off = 16; off > 0; off >>= 1)
        m = fmaxf(m, __shfl_down_sync(0xFFFFFFFFu, m, off));
    if (lane == 0) smax[wid] = m;
    __syncthreads();
    if (threadIdx.x == 0) {
        float bm = 0.f;
        for (int w = 0; w < 16; w++) bm = fmaxf(bm, smax[w]);
        atomicMaxF(&g_S[k], bm);
        if (blockIdx.x == 0) g_d[k] = d;
    }

    if (gwarp < N_NODES) {
        __half2 h01 = __floats2half2_rn(acc.x, acc.y);
        __half2 h23 = __floats2half2_rn(acc.z, acc.w);
        uint2 st;
        st.x = *(unsigned*)&h01;
        st.y = *(unsigned*)&h23;
        ((uint2*)(g_hh + (size_t)(k - 1) * SZ))[gwarp * 32 + lane] = st;
    }
}

// ---------------------------------------------------------------------------
// final combine: out = w0*x + sum_k w_k * 2^{E_k} * stored_k,  E_k = sum d_j
// (w0 term uses the original fp32 x — exact)
// ---------------------------------------------------------------------------
__global__ void __launch_bounds__(256)
combine_kernel(const float* __restrict__ x, float* __restrict__ out) {
    int i = blockIdx.x * blockDim.x + threadIdx.x;   // uint2 / float4 index
    if (i >= SZ / 4) return;

    float f[K_HOPS + 1];
    {
        int E = 0;
        for (int k = 1; k <= K_HOPS; k++) {
            E += g_d[k];
            f[k] = g_w[k] * exp2f((float)E);
        }
        f[0] = g_w[0];
    }

    float4 xv = ((const float4*)x)[i];
    float4 r;
    r.x = f[0] * xv.x; r.y = f[0] * xv.y; r.z = f[0] * xv.z; r.w = f[0] * xv.w;

#pragma unroll
    for (int k = 1; k <= K_HOPS; k++) {
        uint2 u = __ldg(&((const uint2*)(g_hh + (size_t)(k - 1) * SZ))[i]);
        float2 p0 = __half22float2(*(__half2*)&u.x);
        float2 p1 = __half22float2(*(__half2*)&u.y);
        r.x += f[k] * p0.x; r.y += f[k] * p0.y;
        r.z += f[k] * p1.x; r.w += f[k] * p1.y;
    }
    ((float4*)out)[i] = r;
}

// ---------------------------------------------------------------------------
// launch
// ---------------------------------------------------------------------------
extern "C" void kernel_launch(void* const* d_in, const int* in_sizes, int n_in,
                              void* d_out, int out_size) {
    const float* x   = nullptr;
    const float* att = nullptr;
    const void*  ei  = nullptr;
    for (int i = 0; i < n_in; i++) {
        if (in_sizes[i] == SZ)               x   = (const float*)d_in[i];
        else if (in_sizes[i] == K_HOPS + 1)  att = (const float*)d_in[i];
        else if (in_sizes[i] == 2 * N_EDGES) ei  = d_in[i];
    }
    float* out = (float*)d_out;

    prep_kernel<<<1, 32>>>(ei, att);
    quantize_x_kernel<<<296, 256>>>(x);

    zero_deg_kernel<<<(N_NODES + 255) / 256, 256>>>();
    hist_kernel<<<((N_EDGES + 1) / 2 + 255) / 256, 256>>>(ei);
    scan_reduce_kernel<<<N_TILES, SCAN_TILE>>>();
    scan_tiles_kernel<<<1, 128>>>();
    scan_final_kernel<<<N_TILES, SCAN_TILE>>>();
    scatter_kernel<<<((N_EDGES + 1) / 2 + 255) / 256, 256>>>(ei);

    const int prop_blocks = (N_NODES * 32 + 511) / 512;
    for (int k = 1; k <= K_HOPS; k++) {
        prop_kernel<<<prop_blocks, 512>>>(k);
    }

    combine_kernel<<<(SZ / 4 + 255) / 256, 256>>>(x, out);
}

// round 9
// speedup vs baseline: 1.1459x; 1.1459x over previous
#include <cuda_runtime.h>
#include <cuda_fp16.h>

#define N_NODES 50000
#define N_EDGES 625000
#define D_FEAT  128
#define K_HOPS  10
#define SZ      (N_NODES * D_FEAT)

#define SCAN_TILE 512
#define N_TILES   ((N_NODES + SCAN_TILE - 1) / SCAN_TILE)   // 98

// ---------------------------------------------------------------------------
// Scratch (device globals — no allocation allowed anywhere)
// ---------------------------------------------------------------------------
__device__ __half g_hh[(size_t)K_HOPS * SZ];  // h_k (scaled) at slot k-1, 128 MB
__device__ __half g_xh[SZ];                   // fp16(x), 12.8 MB
__device__ int    g_deg[N_NODES];
__device__ int    g_rowptr[N_NODES + 1];
__device__ int    g_cursor[N_NODES];
__device__ int    g_col[N_EDGES];
__device__ float  g_w[K_HOPS + 1];
__device__ int    g_is64;
__device__ int    g_tilesum[N_TILES];
__device__ int    g_tileoff[N_TILES];
__device__ float  g_S[K_HOPS + 1];   // S[k] = max |stored h_k| (S[0] = max|x|)
__device__ int    g_d[K_HOPS + 1];   // per-hop scale exponent d_k
__device__ int    g_maxdeg;

__device__ __forceinline__ void atomicMaxF(float* addr, float v) {
    atomicMax((int*)addr, __float_as_int(v));   // valid: non-negative floats
}

// ---------------------------------------------------------------------------
// 0) dtype detect + softmax(att) + zero per-launch scalars
// ---------------------------------------------------------------------------
__global__ void prep_kernel(const void* ei, const float* __restrict__ att) {
    if (threadIdx.x == 0 && blockIdx.x == 0) {
        const long long* p = (const long long*)ei;
        int is64 = 1;
        for (int i = 0; i < 64; i++) {
            long long v = p[i];
            if (v < 0 || v >= (long long)N_NODES) { is64 = 0; break; }
        }
        g_is64 = is64;

        float m = -1e30f;
        for (int i = 0; i <= K_HOPS; i++) m = fmaxf(m, att[i]);
        float e[K_HOPS + 1];
        float s = 0.f;
        for (int i = 0; i <= K_HOPS; i++) { e[i] = __expf(att[i] - m); s += e[i]; }
        float inv = 1.f / s;
        for (int i = 0; i <= K_HOPS; i++) g_w[i] = e[i] * inv;

        for (int i = 0; i <= K_HOPS; i++) { g_S[i] = 0.f; g_d[i] = 0; }
        g_maxdeg = 0;
    }
}

// fused: x -> fp16 g_xh, and max|x| -> g_S[0]
__global__ void __launch_bounds__(256)
quantize_x_kernel(const float* __restrict__ x) {
    float m = 0.f;
    for (int i = blockIdx.x * blockDim.x + threadIdx.x; i < SZ / 4;
         i += gridDim.x * blockDim.x) {
        float4 v = __ldg(&((const float4*)x)[i]);
        m = fmaxf(m, fmaxf(fmaxf(fabsf(v.x), fabsf(v.y)),
                           fmaxf(fabsf(v.z), fabsf(v.w))));
        __half2 h01 = __floats2half2_rn(v.x, v.y);
        __half2 h23 = __floats2half2_rn(v.z, v.w);
        uint2 st;
        st.x = *(unsigned*)&h01;
        st.y = *(unsigned*)&h23;
        ((uint2*)g_xh)[i] = st;
    }
    for (int off = 16; off > 0; off >>= 1)
        m = fmaxf(m, __shfl_down_sync(0xFFFFFFFFu, m, off));
    if ((threadIdx.x & 31) == 0) atomicMaxF(&g_S[0], m);
}

// ---------------------------------------------------------------------------
// CSR build
// ---------------------------------------------------------------------------
__global__ void zero_deg_kernel() {
    int i = blockIdx.x * blockDim.x + threadIdx.x;
    if (i < N_NODES) g_deg[i] = 0;
}

__global__ void hist_kernel(const void* __restrict__ ei) {
    int t = blockIdx.x * blockDim.x + threadIdx.x;
    int e = t * 2;
    if (e >= N_EDGES) return;
    if (g_is64) {
        const longlong2* p = (const longlong2*)((const long long*)ei + N_EDGES);
        longlong2 d = p[t];
        atomicAdd(&g_deg[(int)d.x], 1);
        if (e + 1 < N_EDGES) atomicAdd(&g_deg[(int)d.y], 1);
    } else {
        const int2* p = (const int2*)((const int*)ei + N_EDGES);
        int2 d = p[t];
        atomicAdd(&g_deg[d.x], 1);
        if (e + 1 < N_EDGES) atomicAdd(&g_deg[d.y], 1);
    }
}

__global__ void __launch_bounds__(SCAN_TILE)
scan_reduce_kernel() {
    __shared__ int wsum[SCAN_TILE / 32];
    int i = blockIdx.x * SCAN_TILE + threadIdx.x;
    int v = (i < N_NODES) ? g_deg[i] : 0;
    int mx = v;
    for (int off = 16; off > 0; off >>= 1) {
        v  += __shfl_down_sync(0xFFFFFFFFu, v,  off);
        mx  = max(mx, __shfl_down_sync(0xFFFFFFFFu, mx, off));
    }
    int wid = threadIdx.x >> 5;
    if ((threadIdx.x & 31) == 0) { wsum[wid] = v; atomicMax(&g_maxdeg, mx); }
    __syncthreads();
    if (wid == 0) {
        int lane = threadIdx.x & 31;
        int s = (lane < SCAN_TILE / 32) ? wsum[lane] : 0;
        for (int off = 16; off > 0; off >>= 1)
            s += __shfl_down_sync(0xFFFFFFFFu, s, off);
        if (lane == 0) g_tilesum[blockIdx.x] = s;
    }
}

__global__ void scan_tiles_kernel() {
    __shared__ int wtot[4];
    int tid  = threadIdx.x;
    int lane = tid & 31;
    int wid  = tid >> 5;
    int v = (tid < N_TILES) ? g_tilesum[tid] : 0;
    int incl = v;
    for (int off = 1; off < 32; off <<= 1) {
        int u = __shfl_up_sync(0xFFFFFFFFu, incl, off);
        if (lane >= off) incl += u;
    }
    if (lane == 31) wtot[wid] = incl;
    __syncthreads();
    int base = 0;
    for (int w = 0; w < wid; w++) base += wtot[w];
    int excl = base + incl - v;
    if (tid < N_TILES) g_tileoff[tid] = excl;
    if (tid == N_TILES - 1) g_rowptr[N_NODES] = excl + v;
}

__global__ void __launch_bounds__(SCAN_TILE)
scan_final_kernel() {
    __shared__ int wtot[SCAN_TILE / 32];
    int i    = blockIdx.x * SCAN_TILE + threadIdx.x;
    int lane = threadIdx.x & 31;
    int wid  = threadIdx.x >> 5;

    int v = (i < N_NODES) ? g_deg[i] : 0;
    int incl = v;
    for (int off = 1; off < 32; off <<= 1) {
        int u = __shfl_up_sync(0xFFFFFFFFu, incl, off);
        if (lane >= off) incl += u;
    }
    if (lane == 31) wtot[wid] = incl;
    __syncthreads();
    if (wid == 0) {
        int s = (lane < SCAN_TILE / 32) ? wtot[lane] : 0;
        int si = s;
        for (int off = 1; off < 32; off <<= 1) {
            int u = __shfl_up_sync(0xFFFFFFFFu, si, off);
            if (lane >= off) si += u;
        }
        if (lane < SCAN_TILE / 32) wtot[lane] = si - s;
    }
    __syncthreads();

    if (i < N_NODES) {
        int excl = g_tileoff[blockIdx.x] + wtot[wid] + incl - v;
        g_rowptr[i] = excl;
        g_cursor[i] = excl;
    }
}

__global__ void scatter_kernel(const void* __restrict__ ei) {
    int t = blockIdx.x * blockDim.x + threadIdx.x;
    int e = t * 2;
    if (e >= N_EDGES) return;
    if (g_is64) {
        const long long* p = (const long long*)ei;
        longlong2 sp = ((const longlong2*)p)[t];
        longlong2 dp = ((const longlong2*)(p + N_EDGES))[t];
        int q0 = atomicAdd(&g_cursor[(int)dp.x], 1);
        g_col[q0] = (int)sp.x;
        if (e + 1 < N_EDGES) {
            int q1 = atomicAdd(&g_cursor[(int)dp.y], 1);
            g_col[q1] = (int)sp.y;
        }
    } else {
        const int* p = (const int*)ei;
        int2 sp = ((const int2*)p)[t];
        int2 dp = ((const int2*)(p + N_EDGES))[t];
        int q0 = atomicAdd(&g_cursor[dp.x], 1);
        g_col[q0] = sp.x;
        if (e + 1 < N_EDGES) {
            int q1 = atomicAdd(&g_cursor[dp.y], 1);
            g_col[q1] = sp.y;
        }
    }
}

// ---------------------------------------------------------------------------
// propagation hop k: HALF-WARP per node, fp16 storage, uint4 (16B) loads.
// A full 256B fp16 row = 16 lanes x uint4, so one warp LDG serves TWO edge
// rows (one per half-warp) -> ~1.56x fewer gather instructions than
// warp-per-node. Tail handled by per-half predication (inactive lanes issue
// no requests). stored_k = (A*stored_{k-1}) * 2^{-d_k}, exact pow2 scaling.
// ---------------------------------------------------------------------------
__global__ void __launch_bounds__(512)
prop_kernel(int k) {
    const int tid  = blockIdx.x * blockDim.x + threadIdx.x;
    const int node = tid >> 4;              // half-warp per node
    const int sub  = threadIdx.x & 15;      // lane within half-warp
    const int lane = threadIdx.x & 31;
    const int wid  = threadIdx.x >> 5;
    __shared__ float smax[16];

    float a[8] = {0.f, 0.f, 0.f, 0.f, 0.f, 0.f, 0.f, 0.f};

    if (node < N_NODES) {
        const __half* hin = (k == 1) ? g_xh : (g_hh + (size_t)(k - 2) * SZ);
        const uint4* __restrict__ hv = (const uint4*)hin;
        const int beg = g_rowptr[node];
        const int end = g_rowptr[node + 1];

        for (int e0 = beg; e0 < end; e0 += 4) {
            const int rem = end - e0;
            int  s[4];
            uint4 u[4];
#pragma unroll
            for (int j = 0; j < 4; j++)
                s[j] = (j < rem) ? __ldg(&g_col[e0 + j]) : 0;
#pragma unroll
            for (int j = 0; j < 4; j++)
                u[j] = (j < rem) ? __ldg(&hv[s[j] * 16 + sub])
                                 : make_uint4(0u, 0u, 0u, 0u);
#pragma unroll
            for (int j = 0; j < 4; j++) {
                float2 p;
                p = __half22float2(*(__half2*)&u[j].x); a[0] += p.x; a[1] += p.y;
                p = __half22float2(*(__half2*)&u[j].y); a[2] += p.x; a[3] += p.y;
                p = __half22float2(*(__half2*)&u[j].z); a[4] += p.x; a[5] += p.y;
                p = __half22float2(*(__half2*)&u[j].w); a[6] += p.x; a[7] += p.y;
            }
        }
    }

    // deterministic per-hop scale from previous hop's measured max
    float bound = g_S[k - 1] * (float)g_maxdeg;
    int d = 0;
    if (bound > 32768.f) d = (int)ceilf(log2f(bound * (1.f / 32768.f)));
    float sc = exp2f(-(float)d);            // exact power of 2
#pragma unroll
    for (int i = 0; i < 8; i++) a[i] *= sc;

    // track max |stored_k| (global max — full-warp reduce covers both nodes)
    float m = 0.f;
#pragma unroll
    for (int i = 0; i < 8; i++) m = fmaxf(m, fabsf(a[i]));
    for (int off = 16; off > 0; off >>= 1)
        m = fmaxf(m, __shfl_down_sync(0xFFFFFFFFu, m, off));
    if (lane == 0) smax[wid] = m;
    __syncthreads();
    if (threadIdx.x == 0) {
        float bm = 0.f;
        for (int w = 0; w < 16; w++) bm = fmaxf(bm, smax[w]);
        atomicMaxF(&g_S[k], bm);
        if (blockIdx.x == 0) g_d[k] = d;
    }

    if (node < N_NODES) {
        __half2 h0 = __floats2half2_rn(a[0], a[1]);
        __half2 h1 = __floats2half2_rn(a[2], a[3]);
        __half2 h2 = __floats2half2_rn(a[4], a[5]);
        __half2 h3 = __floats2half2_rn(a[6], a[7]);
        uint4 st;
        st.x = *(unsigned*)&h0;
        st.y = *(unsigned*)&h1;
        st.z = *(unsigned*)&h2;
        st.w = *(unsigned*)&h3;
        ((uint4*)(g_hh + (size_t)(k - 1) * SZ))[node * 16 + sub] = st;
    }
}

// ---------------------------------------------------------------------------
// final combine: out = w0*x + sum_k w_k * 2^{E_k} * stored_k,  E_k = sum d_j
// (w0 term uses the original fp32 x — exact)
// ---------------------------------------------------------------------------
__global__ void __launch_bounds__(256)
combine_kernel(const float* __restrict__ x, float* __restrict__ out) {
    int i = blockIdx.x * blockDim.x + threadIdx.x;   // uint2 / float4 index
    if (i >= SZ / 4) return;

    float f[K_HOPS + 1];
    {
        int E = 0;
        for (int k = 1; k <= K_HOPS; k++) {
            E += g_d[k];
            f[k] = g_w[k] * exp2f((float)E);
        }
        f[0] = g_w[0];
    }

    float4 xv = ((const float4*)x)[i];
    float4 r;
    r.x = f[0] * xv.x; r.y = f[0] * xv.y; r.z = f[0] * xv.z; r.w = f[0] * xv.w;

#pragma unroll
    for (int k = 1; k <= K_HOPS; k++) {
        uint2 u = __ldg(&((const uint2*)(g_hh + (size_t)(k - 1) * SZ))[i]);
        float2 p0 = __half22float2(*(__half2*)&u.x);
        float2 p1 = __half22float2(*(__half2*)&u.y);
        r.x += f[k] * p0.x; r.y += f[k] * p0.y;
        r.z += f[k] * p1.x; r.w += f[k] * p1.y;
    }
    ((float4*)out)[i] = r;
}

// ---------------------------------------------------------------------------
// launch
// ---------------------------------------------------------------------------
extern "C" void kernel_launch(void* const* d_in, const int* in_sizes, int n_in,
                              void* d_out, int out_size) {
    const float* x   = nullptr;
    const float* att = nullptr;
    const void*  ei  = nullptr;
    for (int i = 0; i < n_in; i++) {
        if (in_sizes[i] == SZ)               x   = (const float*)d_in[i];
        else if (in_sizes[i] == K_HOPS + 1)  att = (const float*)d_in[i];
        else if (in_sizes[i] == 2 * N_EDGES) ei  = d_in[i];
    }
    float* out = (float*)d_out;

    prep_kernel<<<1, 32>>>(ei, att);
    quantize_x_kernel<<<296, 256>>>(x);

    zero_deg_kernel<<<(N_NODES + 255) / 256, 256>>>();
    hist_kernel<<<((N_EDGES + 1) / 2 + 255) / 256, 256>>>(ei);
    scan_reduce_kernel<<<N_TILES, SCAN_TILE>>>();
    scan_tiles_kernel<<<1, 128>>>();
    scan_final_kernel<<<N_TILES, SCAN_TILE>>>();
    scatter_kernel<<<((N_EDGES + 1) / 2 + 255) / 256, 256>>>(ei);

    const int prop_blocks = (N_NODES * 16 + 511) / 512;   // half-warp per node
    for (int k = 1; k <= K_HOPS; k++) {
        prop_kernel<<<prop_blocks, 512>>>(k);
    }

    combine_kernel<<<(SZ / 4 + 255) / 256, 256>>>(x, out);
}

// round 10
// speedup vs baseline: 1.2127x; 1.0582x over previous
#include <cuda_runtime.h>
#include <cuda_fp16.h>

#define N_NODES 50000
#define N_EDGES 625000
#define D_FEAT  128
#define K_HOPS  10
#define SZ      (N_NODES * D_FEAT)

#define SCAN_TILE 512
#define N_TILES   ((N_NODES + SCAN_TILE - 1) / SCAN_TILE)   // 98

// ---------------------------------------------------------------------------
// Scratch (device globals — no allocation allowed anywhere)
// ---------------------------------------------------------------------------
__device__ __half g_hh[(size_t)K_HOPS * SZ];  // h_k (scaled) at slot k-1, 128 MB
__device__ __half g_xh[SZ];                   // fp16(x), 12.8 MB
__device__ int    g_deg[N_NODES];
__device__ int    g_rowptr[N_NODES + 1];
__device__ int    g_cursor[N_NODES];
__device__ int    g_col[N_EDGES];
__device__ float  g_w[K_HOPS + 1];
__device__ int    g_is64;
__device__ int    g_tilesum[N_TILES];
__device__ int    g_tileoff[N_TILES];
__device__ float  g_S0;              // max|x|
__device__ int    g_d[K_HOPS + 1];   // per-hop scale exponent d_k (precomputed)
__device__ int    g_maxdeg;

__device__ __forceinline__ void atomicMaxF(float* addr, float v) {
    atomicMax((int*)addr, __float_as_int(v));   // valid: non-negative floats
}

// ---------------------------------------------------------------------------
// 0) dtype detect + softmax(att) + zero per-launch scalars
// ---------------------------------------------------------------------------
__global__ void prep_kernel(const void* ei, const float* __restrict__ att) {
    if (threadIdx.x == 0 && blockIdx.x == 0) {
        const long long* p = (const long long*)ei;
        int is64 = 1;
        for (int i = 0; i < 64; i++) {
            long long v = p[i];
            if (v < 0 || v >= (long long)N_NODES) { is64 = 0; break; }
        }
        g_is64 = is64;

        float m = -1e30f;
        for (int i = 0; i <= K_HOPS; i++) m = fmaxf(m, att[i]);
        float e[K_HOPS + 1];
        float s = 0.f;
        for (int i = 0; i <= K_HOPS; i++) { e[i] = __expf(att[i] - m); s += e[i]; }
        float inv = 1.f / s;
        for (int i = 0; i <= K_HOPS; i++) g_w[i] = e[i] * inv;

        for (int i = 0; i <= K_HOPS; i++) g_d[i] = 0;
        g_S0 = 0.f;
        g_maxdeg = 0;
    }
}

// fused: x -> fp16 g_xh, and max|x| -> g_S0
__global__ void __launch_bounds__(256)
quantize_x_kernel(const float* __restrict__ x) {
    float m = 0.f;
    for (int i = blockIdx.x * blockDim.x + threadIdx.x; i < SZ / 4;
         i += gridDim.x * blockDim.x) {
        float4 v = __ldg(&((const float4*)x)[i]);
        m = fmaxf(m, fmaxf(fmaxf(fabsf(v.x), fabsf(v.y)),
                           fmaxf(fabsf(v.z), fabsf(v.w))));
        __half2 h01 = __floats2half2_rn(v.x, v.y);
        __half2 h23 = __floats2half2_rn(v.z, v.w);
        uint2 st;
        st.x = *(unsigned*)&h01;
        st.y = *(unsigned*)&h23;
        ((uint2*)g_xh)[i] = st;
    }
    for (int off = 16; off > 0; off >>= 1)
        m = fmaxf(m, __shfl_down_sync(0xFFFFFFFFu, m, off));
    if ((threadIdx.x & 31) == 0) atomicMaxF(&g_S0, m);
}

// deterministic scale plan: bound chain S_k <= S_{k-1}*maxdeg*2^{-d_k}.
// fp16 relative precision is scale-invariant, so the conservative bound
// costs no accuracy; it guarantees no overflow without per-hop measurement.
__global__ void scale_plan_kernel() {
    if (threadIdx.x == 0 && blockIdx.x == 0) {
        float S  = g_S0;
        float md = (float)g_maxdeg;
        for (int k = 1; k <= K_HOPS; k++) {
            float bound = S * md;
            int d = 0;
            if (bound > 32768.f) d = (int)ceilf(log2f(bound * (1.f / 32768.f)));
            g_d[k] = d;
            S = bound * exp2f(-(float)d);
        }
    }
}

// ---------------------------------------------------------------------------
// CSR build
// ---------------------------------------------------------------------------
__global__ void zero_deg_kernel() {
    int i = blockIdx.x * blockDim.x + threadIdx.x;
    if (i < N_NODES) g_deg[i] = 0;
}

__global__ void hist_kernel(const void* __restrict__ ei) {
    int t = blockIdx.x * blockDim.x + threadIdx.x;
    int e = t * 2;
    if (e >= N_EDGES) return;
    if (g_is64) {
        const longlong2* p = (const longlong2*)((const long long*)ei + N_EDGES);
        longlong2 d = p[t];
        atomicAdd(&g_deg[(int)d.x], 1);
        if (e + 1 < N_EDGES) atomicAdd(&g_deg[(int)d.y], 1);
    } else {
        const int2* p = (const int2*)((const int*)ei + N_EDGES);
        int2 d = p[t];
        atomicAdd(&g_deg[d.x], 1);
        if (e + 1 < N_EDGES) atomicAdd(&g_deg[d.y], 1);
    }
}

__global__ void __launch_bounds__(SCAN_TILE)
scan_reduce_kernel() {
    __shared__ int wsum[SCAN_TILE / 32];
    int i = blockIdx.x * SCAN_TILE + threadIdx.x;
    int v = (i < N_NODES) ? g_deg[i] : 0;
    int mx = v;
    for (int off = 16; off > 0; off >>= 1) {
        v  += __shfl_down_sync(0xFFFFFFFFu, v,  off);
        mx  = max(mx, __shfl_down_sync(0xFFFFFFFFu, mx, off));
    }
    int wid = threadIdx.x >> 5;
    if ((threadIdx.x & 31) == 0) { wsum[wid] = v; atomicMax(&g_maxdeg, mx); }
    __syncthreads();
    if (wid == 0) {
        int lane = threadIdx.x & 31;
        int s = (lane < SCAN_TILE / 32) ? wsum[lane] : 0;
        for (int off = 16; off > 0; off >>= 1)
            s += __shfl_down_sync(0xFFFFFFFFu, s, off);
        if (lane == 0) g_tilesum[blockIdx.x] = s;
    }
}

__global__ void scan_tiles_kernel() {
    __shared__ int wtot[4];
    int tid  = threadIdx.x;
    int lane = tid & 31;
    int wid  = tid >> 5;
    int v = (tid < N_TILES) ? g_tilesum[tid] : 0;
    int incl = v;
    for (int off = 1; off < 32; off <<= 1) {
        int u = __shfl_up_sync(0xFFFFFFFFu, incl, off);
        if (lane >= off) incl += u;
    }
    if (lane == 31) wtot[wid] = incl;
    __syncthreads();
    int base = 0;
    for (int w = 0; w < wid; w++) base += wtot[w];
    int excl = base + incl - v;
    if (tid < N_TILES) g_tileoff[tid] = excl;
    if (tid == N_TILES - 1) g_rowptr[N_NODES] = excl + v;
}

__global__ void __launch_bounds__(SCAN_TILE)
scan_final_kernel() {
    __shared__ int wtot[SCAN_TILE / 32];
    int i    = blockIdx.x * SCAN_TILE + threadIdx.x;
    int lane = threadIdx.x & 31;
    int wid  = threadIdx.x >> 5;

    int v = (i < N_NODES) ? g_deg[i] : 0;
    int incl = v;
    for (int off = 1; off < 32; off <<= 1) {
        int u = __shfl_up_sync(0xFFFFFFFFu, incl, off);
        if (lane >= off) incl += u;
    }
    if (lane == 31) wtot[wid] = incl;
    __syncthreads();
    if (wid == 0) {
        int s = (lane < SCAN_TILE / 32) ? wtot[lane] : 0;
        int si = s;
        for (int off = 1; off < 32; off <<= 1) {
            int u = __shfl_up_sync(0xFFFFFFFFu, si, off);
            if (lane >= off) si += u;
        }
        if (lane < SCAN_TILE / 32) wtot[lane] = si - s;
    }
    __syncthreads();

    if (i < N_NODES) {
        int excl = g_tileoff[blockIdx.x] + wtot[wid] + incl - v;
        g_rowptr[i] = excl;
        g_cursor[i] = excl;
    }
}

__global__ void scatter_kernel(const void* __restrict__ ei) {
    int t = blockIdx.x * blockDim.x + threadIdx.x;
    int e = t * 2;
    if (e >= N_EDGES) return;
    if (g_is64) {
        const long long* p = (const long long*)ei;
        longlong2 sp = ((const longlong2*)p)[t];
        longlong2 dp = ((const longlong2*)(p + N_EDGES))[t];
        int q0 = atomicAdd(&g_cursor[(int)dp.x], 1);
        g_col[q0] = (int)sp.x;
        if (e + 1 < N_EDGES) {
            int q1 = atomicAdd(&g_cursor[(int)dp.y], 1);
            g_col[q1] = (int)sp.y;
        }
    } else {
        const int* p = (const int*)ei;
        int2 sp = ((const int2*)p)[t];
        int2 dp = ((const int2*)(p + N_EDGES))[t];
        int q0 = atomicAdd(&g_cursor[dp.x], 1);
        g_col[q0] = sp.x;
        if (e + 1 < N_EDGES) {
            int q1 = atomicAdd(&g_cursor[dp.y], 1);
            g_col[q1] = sp.y;
        }
    }
}

// ---------------------------------------------------------------------------
// propagation hop k: HALF-WARP per node, fp16, uint4 loads, chunk-8 MLP.
// Pure gather kernel — no barriers, no atomics (d_k precomputed).
//   stored_k = (A * stored_{k-1}) * 2^{-d_k}
// ---------------------------------------------------------------------------
__global__ void __launch_bounds__(512)
prop_kernel(int k) {
    const int tid  = blockIdx.x * blockDim.x + threadIdx.x;
    const int node = tid >> 4;              // half-warp per node
    const int sub  = threadIdx.x & 15;      // lane within half-warp
    if (node >= N_NODES) return;

    const __half* hin = (k == 1) ? g_xh : (g_hh + (size_t)(k - 2) * SZ);
    const uint4* __restrict__ hv = (const uint4*)hin;
    const int beg = g_rowptr[node];
    const int end = g_rowptr[node + 1];

    float a[8] = {0.f, 0.f, 0.f, 0.f, 0.f, 0.f, 0.f, 0.f};

    for (int e0 = beg; e0 < end; e0 += 8) {
        const int rem = end - e0;
        int  s[8];
        uint4 u[8];
#pragma unroll
        for (int j = 0; j < 8; j++)
            s[j] = (j < rem) ? __ldg(&g_col[e0 + j]) : 0;
#pragma unroll
        for (int j = 0; j < 8; j++)
            u[j] = (j < rem) ? __ldg(&hv[s[j] * 16 + sub])
                             : make_uint4(0u, 0u, 0u, 0u);
#pragma unroll
        for (int j = 0; j < 8; j++) {
            float2 p;
            p = __half22float2(*(__half2*)&u[j].x); a[0] += p.x; a[1] += p.y;
            p = __half22float2(*(__half2*)&u[j].y); a[2] += p.x; a[3] += p.y;
            p = __half22float2(*(__half2*)&u[j].z); a[4] += p.x; a[5] += p.y;
            p = __half22float2(*(__half2*)&u[j].w); a[6] += p.x; a[7] += p.y;
        }
    }

    const float sc = exp2f(-(float)g_d[k]);   // exact power of 2
#pragma unroll
    for (int i = 0; i < 8; i++) a[i] *= sc;

    __half2 h0 = __floats2half2_rn(a[0], a[1]);
    __half2 h1 = __floats2half2_rn(a[2], a[3]);
    __half2 h2 = __floats2half2_rn(a[4], a[5]);
    __half2 h3 = __floats2half2_rn(a[6], a[7]);
    uint4 st;
    st.x = *(unsigned*)&h0;
    st.y = *(unsigned*)&h1;
    st.z = *(unsigned*)&h2;
    st.w = *(unsigned*)&h3;
    ((uint4*)(g_hh + (size_t)(k - 1) * SZ))[node * 16 + sub] = st;
}

// ---------------------------------------------------------------------------
// final combine: out = w0*x + sum_k w_k * 2^{E_k} * stored_k,  E_k = sum d_j
// (w0 term uses the original fp32 x — exact)
// ---------------------------------------------------------------------------
__global__ void __launch_bounds__(256)
combine_kernel(const float* __restrict__ x, float* __restrict__ out) {
    int i = blockIdx.x * blockDim.x + threadIdx.x;   // uint2 / float4 index
    if (i >= SZ / 4) return;

    float f[K_HOPS + 1];
    {
        int E = 0;
        for (int k = 1; k <= K_HOPS; k++) {
            E += g_d[k];
            f[k] = g_w[k] * exp2f((float)E);
        }
        f[0] = g_w[0];
    }

    float4 xv = ((const float4*)x)[i];
    float4 r;
    r.x = f[0] * xv.x; r.y = f[0] * xv.y; r.z = f[0] * xv.z; r.w = f[0] * xv.w;

#pragma unroll
    for (int k = 1; k <= K_HOPS; k++) {
        uint2 u = __ldg(&((const uint2*)(g_hh + (size_t)(k - 1) * SZ))[i]);
        float2 p0 = __half22float2(*(__half2*)&u.x);
        float2 p1 = __half22float2(*(__half2*)&u.y);
        r.x += f[k] * p0.x; r.y += f[k] * p0.y;
        r.z += f[k] * p1.x; r.w += f[k] * p1.y;
    }
    ((float4*)out)[i] = r;
}

// ---------------------------------------------------------------------------
// launch
// ---------------------------------------------------------------------------
extern "C" void kernel_launch(void* const* d_in, const int* in_sizes, int n_in,
                              void* d_out, int out_size) {
    const float* x   = nullptr;
    const float* att = nullptr;
    const void*  ei  = nullptr;
    for (int i = 0; i < n_in; i++) {
        if (in_sizes[i] == SZ)               x   = (const float*)d_in[i];
        else if (in_sizes[i] == K_HOPS + 1)  att = (const float*)d_in[i];
        else if (in_sizes[i] == 2 * N_EDGES) ei  = d_in[i];
    }
    float* out = (float*)d_out;

    prep_kernel<<<1, 32>>>(ei, att);
    quantize_x_kernel<<<296, 256>>>(x);

    zero_deg_kernel<<<(N_NODES + 255) / 256, 256>>>();
    hist_kernel<<<((N_EDGES + 1) / 2 + 255) / 256, 256>>>(ei);
    scan_reduce_kernel<<<N_TILES, SCAN_TILE>>>();
    scan_tiles_kernel<<<1, 128>>>();
    scan_final_kernel<<<N_TILES, SCAN_TILE>>>();
    scatter_kernel<<<((N_EDGES + 1) / 2 + 255) / 256, 256>>>(ei);

    scale_plan_kernel<<<1, 32>>>();   // needs g_S0 (quantize) + g_maxdeg (scan_reduce)

    const int prop_blocks = (N_NODES * 16 + 511) / 512;   // half-warp per node
    for (int k = 1; k <= K_HOPS; k++) {
        prop_kernel<<<prop_blocks, 512>>>(k);
    }

    combine_kernel<<<(SZ / 4 + 255) / 256, 256>>>(x, out);
}

// round 11
// speedup vs baseline: 1.2139x; 1.0010x over previous
#include <cuda_runtime.h>
#include <cuda_fp16.h>

#define N_NODES 50000
#define N_EDGES 625000
#define D_FEAT  128
#define K_HOPS  10
#define SZ      (N_NODES * D_FEAT)

#define SCAN_TILE 512
#define N_TILES   ((N_NODES + SCAN_TILE - 1) / SCAN_TILE)   // 98

// ---------------------------------------------------------------------------
// Scratch (device globals — no allocation allowed anywhere)
// ---------------------------------------------------------------------------
__device__ __half g_hh[(size_t)K_HOPS * SZ];  // h_k (scaled) at slot k-1, 128 MB
__device__ __half g_xh[SZ];                   // fp16(x), 12.8 MB
__device__ int    g_deg[N_NODES];
__device__ int    g_rowptr[N_NODES + 1];
__device__ int    g_cursor[N_NODES];
__device__ int    g_col[N_EDGES];
__device__ float  g_w[K_HOPS + 1];
__device__ int    g_is64;
__device__ int    g_tilesum[N_TILES];
__device__ int    g_tileoff[N_TILES];
__device__ float  g_S0;              // max|x|
__device__ int    g_d[K_HOPS + 1];   // per-hop scale exponent d_k (precomputed)
__device__ int    g_maxdeg;

__device__ __forceinline__ void atomicMaxF(float* addr, float v) {
    atomicMax((int*)addr, __float_as_int(v));   // valid: non-negative floats
}

// ---------------------------------------------------------------------------
// 0) dtype detect + softmax(att) + zero per-launch scalars
// ---------------------------------------------------------------------------
__global__ void prep_kernel(const void* ei, const float* __restrict__ att) {
    if (threadIdx.x == 0 && blockIdx.x == 0) {
        const long long* p = (const long long*)ei;
        int is64 = 1;
        for (int i = 0; i < 64; i++) {
            long long v = p[i];
            if (v < 0 || v >= (long long)N_NODES) { is64 = 0; break; }
        }
        g_is64 = is64;

        float m = -1e30f;
        for (int i = 0; i <= K_HOPS; i++) m = fmaxf(m, att[i]);
        float e[K_HOPS + 1];
        float s = 0.f;
        for (int i = 0; i <= K_HOPS; i++) { e[i] = __expf(att[i] - m); s += e[i]; }
        float inv = 1.f / s;
        for (int i = 0; i <= K_HOPS; i++) g_w[i] = e[i] * inv;

        for (int i = 0; i <= K_HOPS; i++) g_d[i] = 0;
        g_S0 = 0.f;
        g_maxdeg = 0;
    }
}

// fused: x -> fp16 g_xh, max|x| -> g_S0, AND zero g_deg (saves a launch)
__global__ void __launch_bounds__(256)
quantize_x_kernel(const float* __restrict__ x) {
    const int stride = gridDim.x * blockDim.x;
    int t = blockIdx.x * blockDim.x + threadIdx.x;

    for (int i = t; i < N_NODES; i += stride) g_deg[i] = 0;

    float m = 0.f;
    for (int i = t; i < SZ / 4; i += stride) {
        float4 v = __ldg(&((const float4*)x)[i]);
        m = fmaxf(m, fmaxf(fmaxf(fabsf(v.x), fabsf(v.y)),
                           fmaxf(fabsf(v.z), fabsf(v.w))));
        __half2 h01 = __floats2half2_rn(v.x, v.y);
        __half2 h23 = __floats2half2_rn(v.z, v.w);
        uint2 st;
        st.x = *(unsigned*)&h01;
        st.y = *(unsigned*)&h23;
        ((uint2*)g_xh)[i] = st;
    }
    for (int off = 16; off > 0; off >>= 1)
        m = fmaxf(m, __shfl_down_sync(0xFFFFFFFFu, m, off));
    if ((threadIdx.x & 31) == 0) atomicMaxF(&g_S0, m);
}

// ---------------------------------------------------------------------------
// CSR build
// ---------------------------------------------------------------------------

// 4 edges per thread, vectorized dst loads
__global__ void hist_kernel(const void* __restrict__ ei) {
    int t = blockIdx.x * blockDim.x + threadIdx.x;
    int e = t * 4;
    if (e >= N_EDGES) return;
    int d0, d1, d2, d3;
    if (g_is64) {
        const longlong2* p = (const longlong2*)((const long long*)ei + N_EDGES);
        longlong2 a = p[t * 2];
        longlong2 b = p[t * 2 + 1];
        d0 = (int)a.x; d1 = (int)a.y; d2 = (int)b.x; d3 = (int)b.y;
    } else {
        int4 a = ((const int4*)((const int*)ei + N_EDGES))[t];
        d0 = a.x; d1 = a.y; d2 = a.z; d3 = a.w;
    }
    atomicAdd(&g_deg[d0], 1);
    if (e + 1 < N_EDGES) atomicAdd(&g_deg[d1], 1);
    if (e + 2 < N_EDGES) atomicAdd(&g_deg[d2], 1);
    if (e + 3 < N_EDGES) atomicAdd(&g_deg[d3], 1);
}

__global__ void __launch_bounds__(SCAN_TILE)
scan_reduce_kernel() {
    __shared__ int wsum[SCAN_TILE / 32];
    int i = blockIdx.x * SCAN_TILE + threadIdx.x;
    int v = (i < N_NODES) ? g_deg[i] : 0;
    int mx = v;
    for (int off = 16; off > 0; off >>= 1) {
        v  += __shfl_down_sync(0xFFFFFFFFu, v,  off);
        mx  = max(mx, __shfl_down_sync(0xFFFFFFFFu, mx, off));
    }
    int wid = threadIdx.x >> 5;
    if ((threadIdx.x & 31) == 0) { wsum[wid] = v; atomicMax(&g_maxdeg, mx); }
    __syncthreads();
    if (wid == 0) {
        int lane = threadIdx.x & 31;
        int s = (lane < SCAN_TILE / 32) ? wsum[lane] : 0;
        for (int off = 16; off > 0; off >>= 1)
            s += __shfl_down_sync(0xFFFFFFFFu, s, off);
        if (lane == 0) g_tilesum[blockIdx.x] = s;
    }
}

// tile-sum exclusive scan + fused deterministic scale plan (thread 0 tail)
__global__ void scan_tiles_kernel() {
    __shared__ int wtot[4];
    int tid  = threadIdx.x;
    int lane = tid & 31;
    int wid  = tid >> 5;
    int v = (tid < N_TILES) ? g_tilesum[tid] : 0;
    int incl = v;
    for (int off = 1; off < 32; off <<= 1) {
        int u = __shfl_up_sync(0xFFFFFFFFu, incl, off);
        if (lane >= off) incl += u;
    }
    if (lane == 31) wtot[wid] = incl;
    __syncthreads();
    int base = 0;
    for (int w = 0; w < wid; w++) base += wtot[w];
    int excl = base + incl - v;
    if (tid < N_TILES) g_tileoff[tid] = excl;
    if (tid == N_TILES - 1) g_rowptr[N_NODES] = excl + v;

    // scale plan: bound chain S_k <= S_{k-1}*maxdeg*2^{-d_k}. fp16 relative
    // precision is scale-invariant, so the conservative bound costs nothing;
    // it guarantees no overflow without per-hop measurement.
    if (tid == 0) {
        float S  = g_S0;                 // ready (quantize precedes in stream)
        float md = (float)g_maxdeg;      // ready (scan_reduce precedes)
        for (int k = 1; k <= K_HOPS; k++) {
            float bound = S * md;
            int d = 0;
            if (bound > 32768.f) d = (int)ceilf(log2f(bound * (1.f / 32768.f)));
            g_d[k] = d;
            S = bound * exp2f(-(float)d);
        }
    }
}

__global__ void __launch_bounds__(SCAN_TILE)
scan_final_kernel() {
    __shared__ int wtot[SCAN_TILE / 32];
    int i    = blockIdx.x * SCAN_TILE + threadIdx.x;
    int lane = threadIdx.x & 31;
    int wid  = threadIdx.x >> 5;

    int v = (i < N_NODES) ? g_deg[i] : 0;
    int incl = v;
    for (int off = 1; off < 32; off <<= 1) {
        int u = __shfl_up_sync(0xFFFFFFFFu, incl, off);
        if (lane >= off) incl += u;
    }
    if (lane == 31) wtot[wid] = incl;
    __syncthreads();
    if (wid == 0) {
        int s = (lane < SCAN_TILE / 32) ? wtot[lane] : 0;
        int si = s;
        for (int off = 1; off < 32; off <<= 1) {
            int u = __shfl_up_sync(0xFFFFFFFFu, si, off);
            if (lane >= off) si += u;
        }
        if (lane < SCAN_TILE / 32) wtot[lane] = si - s;
    }
    __syncthreads();

    if (i < N_NODES) {
        int excl = g_tileoff[blockIdx.x] + wtot[wid] + incl - v;
        g_rowptr[i] = excl;
        g_cursor[i] = excl;
    }
}

// 4 edges per thread, vectorized src/dst loads
__global__ void scatter_kernel(const void* __restrict__ ei) {
    int t = blockIdx.x * blockDim.x + threadIdx.x;
    int e = t * 4;
    if (e >= N_EDGES) return;
    int s0, s1, s2, s3, d0, d1, d2, d3;
    if (g_is64) {
        const long long* p = (const long long*)ei;
        longlong2 sa = ((const longlong2*)p)[t * 2];
        longlong2 sb = ((const longlong2*)p)[t * 2 + 1];
        longlong2 da = ((const longlong2*)(p + N_EDGES))[t * 2];
        longlong2 db = ((const longlong2*)(p + N_EDGES))[t * 2 + 1];
        s0 = (int)sa.x; s1 = (int)sa.y; s2 = (int)sb.x; s3 = (int)sb.y;
        d0 = (int)da.x; d1 = (int)da.y; d2 = (int)db.x; d3 = (int)db.y;
    } else {
        const int* p = (const int*)ei;
        int4 sa = ((const int4*)p)[t];
        int4 da = ((const int4*)(p + N_EDGES))[t];
        s0 = sa.x; s1 = sa.y; s2 = sa.z; s3 = sa.w;
        d0 = da.x; d1 = da.y; d2 = da.z; d3 = da.w;
    }
    { int q = atomicAdd(&g_cursor[d0], 1); g_col[q] = s0; }
    if (e + 1 < N_EDGES) { int q = atomicAdd(&g_cursor[d1], 1); g_col[q] = s1; }
    if (e + 2 < N_EDGES) { int q = atomicAdd(&g_cursor[d2], 1); g_col[q] = s2; }
    if (e + 3 < N_EDGES) { int q = atomicAdd(&g_cursor[d3], 1); g_col[q] = s3; }
}

// ---------------------------------------------------------------------------
// propagation hop k: HALF-WARP per node, fp16, uint4 loads, chunk-8 MLP.
// Pure gather kernel — no barriers, no atomics (d_k precomputed).
//   stored_k = (A * stored_{k-1}) * 2^{-d_k}
// ---------------------------------------------------------------------------
__global__ void __launch_bounds__(512)
prop_kernel(int k) {
    const int tid  = blockIdx.x * blockDim.x + threadIdx.x;
    const int node = tid >> 4;              // half-warp per node
    const int sub  = threadIdx.x & 15;      // lane within half-warp
    if (node >= N_NODES) return;

    const __half* hin = (k == 1) ? g_xh : (g_hh + (size_t)(k - 2) * SZ);
    const uint4* __restrict__ hv = (const uint4*)hin;
    const int beg = g_rowptr[node];
    const int end = g_rowptr[node + 1];

    float a[8] = {0.f, 0.f, 0.f, 0.f, 0.f, 0.f, 0.f, 0.f};

    for (int e0 = beg; e0 < end; e0 += 8) {
        const int rem = end - e0;
        int  s[8];
        uint4 u[8];
#pragma unroll
        for (int j = 0; j < 8; j++)
            s[j] = (j < rem) ? __ldg(&g_col[e0 + j]) : 0;
#pragma unroll
        for (int j = 0; j < 8; j++)
            u[j] = (j < rem) ? __ldg(&hv[s[j] * 16 + sub])
                             : make_uint4(0u, 0u, 0u, 0u);
#pragma unroll
        for (int j = 0; j < 8; j++) {
            float2 p;
            p = __half22float2(*(__half2*)&u[j].x); a[0] += p.x; a[1] += p.y;
            p = __half22float2(*(__half2*)&u[j].y); a[2] += p.x; a[3] += p.y;
            p = __half22float2(*(__half2*)&u[j].z); a[4] += p.x; a[5] += p.y;
            p = __half22float2(*(__half2*)&u[j].w); a[6] += p.x; a[7] += p.y;
        }
    }

    const float sc = exp2f(-(float)g_d[k]);   // exact power of 2
#pragma unroll
    for (int i = 0; i < 8; i++) a[i] *= sc;

    __half2 h0 = __floats2half2_rn(a[0], a[1]);
    __half2 h1 = __floats2half2_rn(a[2], a[3]);
    __half2 h2 = __floats2half2_rn(a[4], a[5]);
    __half2 h3 = __floats2half2_rn(a[6], a[7]);
    uint4 st;
    st.x = *(unsigned*)&h0;
    st.y = *(unsigned*)&h1;
    st.z = *(unsigned*)&h2;
    st.w = *(unsigned*)&h3;
    ((uint4*)(g_hh + (size_t)(k - 1) * SZ))[node * 16 + sub] = st;
}

// ---------------------------------------------------------------------------
// final combine: out = w0*x + sum_k w_k * 2^{E_k} * stored_k,  E_k = sum d_j
// 8 floats per thread, uint4 slot loads (halves LDG count vs uint2).
// ---------------------------------------------------------------------------
__global__ void __launch_bounds__(256)
combine_kernel(const float* __restrict__ x, float* __restrict__ out) {
    int i = blockIdx.x * blockDim.x + threadIdx.x;   // uint4 index (8 halves)
    if (i >= SZ / 8) return;

    float f[K_HOPS + 1];
    {
        int E = 0;
        for (int k = 1; k <= K_HOPS; k++) {
            E += g_d[k];
            f[k] = g_w[k] * exp2f((float)E);
        }
        f[0] = g_w[0];
    }

    float4 xa = ((const float4*)x)[i * 2];
    float4 xb = ((const float4*)x)[i * 2 + 1];
    float4 ra, rb;
    ra.x = f[0] * xa.x; ra.y = f[0] * xa.y; ra.z = f[0] * xa.z; ra.w = f[0] * xa.w;
    rb.x = f[0] * xb.x; rb.y = f[0] * xb.y; rb.z = f[0] * xb.z; rb.w = f[0] * xb.w;

#pragma unroll
    for (int k = 1; k <= K_HOPS; k++) {
        uint4 u = __ldg(&((const uint4*)(g_hh + (size_t)(k - 1) * SZ))[i]);
        float2 p0 = __half22float2(*(__half2*)&u.x);
        float2 p1 = __half22float2(*(__half2*)&u.y);
        float2 p2 = __half22float2(*(__half2*)&u.z);
        float2 p3 = __half22float2(*(__half2*)&u.w);
        ra.x += f[k] * p0.x; ra.y += f[k] * p0.y;
        ra.z += f[k] * p1.x; ra.w += f[k] * p1.y;
        rb.x += f[k] * p2.x; rb.y += f[k] * p2.y;
        rb.z += f[k] * p3.x; rb.w += f[k] * p3.y;
    }
    ((float4*)out)[i * 2]     = ra;
    ((float4*)out)[i * 2 + 1] = rb;
}

// ---------------------------------------------------------------------------
// launch
// ---------------------------------------------------------------------------
extern "C" void kernel_launch(void* const* d_in, const int* in_sizes, int n_in,
                              void* d_out, int out_size) {
    const float* x   = nullptr;
    const float* att = nullptr;
    const void*  ei  = nullptr;
    for (int i = 0; i < n_in; i++) {
        if (in_sizes[i] == SZ)               x   = (const float*)d_in[i];
        else if (in_sizes[i] == K_HOPS + 1)  att = (const float*)d_in[i];
        else if (in_sizes[i] == 2 * N_EDGES) ei  = d_in[i];
    }
    float* out = (float*)d_out;

    prep_kernel<<<1, 32>>>(ei, att);
    quantize_x_kernel<<<296, 256>>>(x);   // also zeros g_deg

    hist_kernel<<<((N_EDGES + 3) / 4 + 255) / 256, 256>>>(ei);
    scan_reduce_kernel<<<N_TILES, SCAN_TILE>>>();
    scan_tiles_kernel<<<1, 128>>>();      // also computes scale plan
    scan_final_kernel<<<N_TILES, SCAN_TILE>>>();
    scatter_kernel<<<((N_EDGES + 3) / 4 + 255) / 256, 256>>>(ei);

    const int prop_blocks = (N_NODES * 16 + 511) / 512;   // half-warp per node
    for (int k = 1; k <= K_HOPS; k++) {
        prop_kernel<<<prop_blocks, 512>>>(k);
    }

    combine_kernel<<<(SZ / 8 + 255) / 256, 256>>>(x, out);
}